// round 3
// baseline (speedup 1.0000x reference)
#include <cuda_runtime.h>

// ---------------------------------------------------------------------------
// B=16, H=W=1024, ROUTE=(512,256) -> ph=2, pw=4, L=8, NPATCH=128
// scale i: W_i=1024>>i, kh=512>>i, kw=256>>i
// out: [0]=loss, [1..16M]=out_img, [16M+1..32M]=lab_img
// ---------------------------------------------------------------------------

#define NPATCH 128
#define IMG0   16777216
#define NSLOTS 5504   // 4096 + 1024 + 256 + 128 partial slots

__device__ double g_pA[NSLOTS];
__device__ double g_pC[NSLOTS];
__device__ double g_pQ[NSLOTS];
__device__ int    g_mask[NPATCH];

// ---------------------------------------------------------------------------
// Fused per-patch reduction over all 4 scales, constant-stride addressing.
//   scale0: blocks [0,4096)    32/patch, 4 iters
//   scale1: blocks [4096,5120)  8/patch, 4 iters
//   scale2: blocks [5120,5376)  2/patch, 4 iters
//   scale3: blocks [5376,5504)  1/patch, 2 iters
// Every iteration advances exactly 4096 elements for every scale.
__global__ void k_reduce(const float* __restrict__ p0, const float* __restrict__ p1,
                         const float* __restrict__ p2, const float* __restrict__ p3,
                         const float* __restrict__ g0, const float* __restrict__ g1,
                         const float* __restrict__ g2, const float* __restrict__ g3)
{
    int bid = blockIdx.x;
    int scale, base;
    if      (bid < 4096) { scale = 0; base = 0;    }
    else if (bid < 5120) { scale = 1; base = 4096; }
    else if (bid < 5376) { scale = 2; base = 5120; }
    else                 { scale = 3; base = 5376; }
    int rel = bid - base;

    const int kwS_t[4]  = {8, 7, 6, 5};   // log2 kw
    const int wS_t[4]   = {10, 9, 8, 7};  // log2 W
    const int bppS_t[4] = {5, 3, 1, 0};   // log2 blocks-per-patch

    int kwS  = kwS_t[scale];
    int wS   = wS_t[scale];
    int bppS = bppS_t[scale];

    const float* pre = (scale == 0) ? p0 : (scale == 1) ? p1 : (scale == 2) ? p2 : p3;
    const float* gt  = (scale == 0) ? g0 : (scale == 1) ? g1 : (scale == 2) ? g2 : g3;

    int patch = rel >> bppS;
    int slice = rel & ((1 << bppS) - 1);
    int b  = patch >> 3;
    int pr = (patch >> 2) & 1;
    int pc = patch & 3;

    int qpwS = kwS - 2;                        // log2 quads-per-row
    int row  = threadIdx.x >> qpwS;
    int col4 = (threadIdx.x & ((1 << qpwS) - 1)) << 2;
    int rpi  = 256 >> qpwS;                    // rows per iteration
    int rpb  = rpi << 2;                       // rows per block at 4 iters
    if (scale == 3) rpb = rpi << 1;            // scale3 does 2 iters

    int kh  = 512 >> scale;
    int gy  = pr * kh + slice * rpb + row;
    int gx  = (pc << kwS) + col4;
    int idx = (b << (2 * wS)) + (gy << wS) + gx;

    float sg = 0.f, spp = 0.f, cnt = 0.f, ssq = 0.f;

    #define ACC(pp, gg) { float e = fmaf((gg), -200.0f, (pp));       \
                          ssq = fmaf(e, e, ssq); sg += (gg);         \
                          if (e < 0.0f) { cnt += 1.0f; spp += (pp); } }
    #define BODY(IT) { const float4 p = *(const float4*)(pre + idx + (IT) * 4096); \
                       const float4 g = *(const float4*)(gt  + idx + (IT) * 4096); \
                       ACC(p.x, g.x) ACC(p.y, g.y) ACC(p.z, g.z) ACC(p.w, g.w) }

    BODY(0) BODY(1)
    if (scale != 3) { BODY(2) BODY(3) }
    #undef BODY
    #undef ACC

    // tail: fp32 smem, single sync, warp0 finishes in double
    __shared__ float fA[256], fC[256], fQ[256];
    int tid = threadIdx.x;
    fA[tid] = fmaf(sg, 200.0f, -spp);          // sabs = 200*Sum(g) - Sum_pos(p)
    fC[tid] = cnt;
    fQ[tid] = ssq;
    __syncthreads();

    if (tid < 32) {
        double dA = 0.0, dC = 0.0, dQ = 0.0;
        #pragma unroll
        for (int j = 0; j < 8; ++j) {
            int k = tid + (j << 5);
            dA += (double)fA[k];
            dC += (double)fC[k];
            dQ += (double)fQ[k];
        }
        #pragma unroll
        for (int off = 16; off > 0; off >>= 1) {
            dA += __shfl_down_sync(0xffffffffu, dA, off);
            dC += __shfl_down_sync(0xffffffffu, dC, off);
            dQ += __shfl_down_sync(0xffffffffu, dQ, off);
        }
        if (tid == 0) {
            g_pA[bid] = dA;
            g_pC[bid] = dC;
            g_pQ[bid] = dQ;
        }
    }
}

// ---------------------------------------------------------------------------
// Per-patch argmin + weighted loss. 1 block, 128 threads (one per patch).
__global__ void k_select(float* __restrict__ out)
{
    int t = threadIdx.x;
    __shared__ double num[4];
    __shared__ int    cnt[4];
    if (t < 4) { num[t] = 0.0; cnt[t] = 0; }
    __syncthreads();

    const int base4[4] = {0, 4096, 5120, 5376};
    const int cnt4[4]  = {32, 8, 2, 1};

    double best = 1e300;
    int mi = 0;
    double ssqs[4];
    #pragma unroll
    for (int i = 0; i < 4; ++i) {
        double A = 0.0, C = 0.0, Q = 0.0;
        int s0 = base4[i] + t * cnt4[i];
        for (int s = 0; s < cnt4[i]; ++s) {
            A += g_pA[s0 + s];
            C += g_pC[s0 + s];
            Q += g_pQ[s0 + s];
        }
        ssqs[i] = Q;
        double e = A / (C + (double)0.1f);
        if (e < best) { best = e; mi = i; }   // strict < = first-min (argmin)
    }
    g_mask[t] = mi;
    atomicAdd(&num[mi], ssqs[mi]);
    atomicAdd(&cnt[mi], 1);
    __syncthreads();

    if (t == 0) {
        const double w[4]  = {0.5, 0.25, 0.125, 0.0625};
        const double pe[4] = {131072.0, 32768.0, 8192.0, 2048.0};
        double loss = 0.0;
        #pragma unroll
        for (int i = 0; i < 4; ++i)
            loss += w[i] * (num[i] / ((double)cnt[i] * pe[i] + (double)0.01f));
        out[0] = (float)loss;
    }
}

// ---------------------------------------------------------------------------
// Compose out_img & lab_img. One block = two 1024-pixel rows (2048 px),
// 2 quads per thread for MLP. Values staged in smem, then emitted with
// ALIGNED float4 streaming stores despite the +1 global offset.
__global__ void k_write(const float* __restrict__ p0, const float* __restrict__ p1,
                        const float* __restrict__ p2, const float* __restrict__ p3,
                        const float* __restrict__ g0, const float* __restrict__ g1,
                        const float* __restrict__ g2, const float* __restrict__ g3,
                        float* __restrict__ out)
{
    __shared__ float so[2048];
    __shared__ float sl[2048];

    int t    = threadIdx.x;
    int base = blockIdx.x << 11;          // 2048-pixel chunk (2 rows)

    #pragma unroll
    for (int j = 0; j < 2; ++j) {
        int P  = base + (t << 2) + (j << 10);
        int b  = P >> 20;
        int r  = P & 1048575;
        int Y  = r >> 10;
        int X  = r & 1023;
        int pr = Y >> 9;
        int pc = X >> 8;
        int mi = g_mask[(b << 3) | (pr << 2) | pc];

        int kh = 512 >> mi;
        int kw = 256 >> mi;
        int iy = (Y & 511) - ((512 - kh) >> 1);
        int ix = (X & 255) - ((256 - kw) >> 1);

        const float PADV = 0.2f / 200.0f;
        float4 vo = make_float4(PADV, PADV, PADV, PADV);
        float4 vl = vo;

        if ((unsigned)iy < (unsigned)kh && (unsigned)ix < (unsigned)kw) {
            int ws  = 10 - mi;
            int idx = (b << (2 * ws)) + ((pr * kh + iy) << ws)
                    + (pc << (8 - mi)) + ix;
            const float* pp = (mi == 0) ? p0 : (mi == 1) ? p1 : (mi == 2) ? p2 : p3;
            const float* gg = (mi == 0) ? g0 : (mi == 1) ? g1 : (mi == 2) ? g2 : g3;
            float4 p = *(const float4*)(pp + idx);
            float4 g = *(const float4*)(gg + idx);
            vo = make_float4(p.x / 200.0f, p.y / 200.0f, p.z / 200.0f, p.w / 200.0f);
            vl = make_float4((g.x * 200.0f) / 200.0f, (g.y * 200.0f) / 200.0f,
                             (g.z * 200.0f) / 200.0f, (g.w * 200.0f) / 200.0f);
        }

        *(float4*)(so + (t << 2) + (j << 10)) = vo;
        *(float4*)(sl + (t << 2) + (j << 10)) = vl;
    }
    __syncthreads();

    float* ob = out + 1 + base;           // +1 offset: quads at k=3+4q aligned
    float* lb = ob + IMG0;                // IMG0 % 4 == 0 -> same phase

    #pragma unroll
    for (int j = 0; j < 2; ++j) {
        int q = (t << 1) + j;             // 0..511
        if (q < 511) {
            int k = 3 + (q << 2);
            float4 a = make_float4(so[k], so[k + 1], so[k + 2], so[k + 3]);
            float4 c = make_float4(sl[k], sl[k + 1], sl[k + 2], sl[k + 3]);
            __stcs((float4*)(ob + k), a);
            __stcs((float4*)(lb + k), c);
        } else {
            ob[0] = so[0]; ob[1] = so[1]; ob[2] = so[2]; ob[2047] = so[2047];
            lb[0] = sl[0]; lb[1] = sl[1]; lb[2] = sl[2]; lb[2047] = sl[2047];
        }
    }
}

// ---------------------------------------------------------------------------
extern "C" void kernel_launch(void* const* d_in, const int* in_sizes, int n_in,
                              void* d_out, int out_size)
{
    const float *pre[4], *gt[4];
    if (n_in >= 8 && in_sizes[1] == in_sizes[0]) {        // interleaved
        for (int i = 0; i < 4; ++i) {
            pre[i] = (const float*)d_in[2 * i];
            gt [i] = (const float*)d_in[2 * i + 1];
        }
    } else {                                              // grouped
        for (int i = 0; i < 4; ++i) {
            pre[i] = (const float*)d_in[i];
            gt [i] = (const float*)d_in[4 + i];
        }
    }
    float* out = (float*)d_out;

    k_reduce<<<NSLOTS, 256>>>(pre[0], pre[1], pre[2], pre[3],
                              gt[0], gt[1], gt[2], gt[3]);
    k_select<<<1, 128>>>(out);
    k_write<<<8192, 256>>>(pre[0], pre[1], pre[2], pre[3],
                           gt[0], gt[1], gt[2], gt[3], out);
    (void)out_size;
}

// round 4
// speedup vs baseline: 1.1935x; 1.1935x over previous
#include <cuda_runtime.h>

// ---------------------------------------------------------------------------
// B=16, H=W=1024, ROUTE=(512,256) -> ph=2, pw=4, L=8, NPATCH=128
// scale i: W_i=1024>>i, kh=512>>i, kw=256>>i
// out: [0]=loss, [1..16M]=out_img, [16M+1..32M]=lab_img
// ---------------------------------------------------------------------------

#define NPATCH 128
#define IMG0   16777216
#define NSLOTS 5504   // 4096 + 1024 + 256 + 128 partial slots

__device__ double g_pA[NSLOTS];
__device__ double g_pC[NSLOTS];
__device__ double g_pQ[NSLOTS];
__device__ int    g_mask[NPATCH];

// ---------------------------------------------------------------------------
// Fused per-patch reduction over all 4 scales, constant-stride addressing,
// loads front-batched for MLP (up to 8 LDG.128 in flight per thread).
//   scale0: blocks [0,4096)    32/patch, 4 iters
//   scale1: blocks [4096,5120)  8/patch, 4 iters
//   scale2: blocks [5120,5376)  2/patch, 4 iters
//   scale3: blocks [5376,5504)  1/patch, 2 iters
__global__ void __launch_bounds__(256, 4)
k_reduce(const float* __restrict__ p0, const float* __restrict__ p1,
         const float* __restrict__ p2, const float* __restrict__ p3,
         const float* __restrict__ g0, const float* __restrict__ g1,
         const float* __restrict__ g2, const float* __restrict__ g3)
{
    int bid = blockIdx.x;
    int scale, base;
    if      (bid < 4096) { scale = 0; base = 0;    }
    else if (bid < 5120) { scale = 1; base = 4096; }
    else if (bid < 5376) { scale = 2; base = 5120; }
    else                 { scale = 3; base = 5376; }
    int rel = bid - base;

    const int kwS_t[4]  = {8, 7, 6, 5};   // log2 kw
    const int wS_t[4]   = {10, 9, 8, 7};  // log2 W
    const int bppS_t[4] = {5, 3, 1, 0};   // log2 blocks-per-patch

    int kwS  = kwS_t[scale];
    int wS   = wS_t[scale];
    int bppS = bppS_t[scale];

    const float* pre = (scale == 0) ? p0 : (scale == 1) ? p1 : (scale == 2) ? p2 : p3;
    const float* gt  = (scale == 0) ? g0 : (scale == 1) ? g1 : (scale == 2) ? g2 : g3;

    int patch = rel >> bppS;
    int slice = rel & ((1 << bppS) - 1);
    int b  = patch >> 3;
    int pr = (patch >> 2) & 1;
    int pc = patch & 3;

    int qpwS = kwS - 2;                        // log2 quads-per-row
    int row  = threadIdx.x >> qpwS;
    int col4 = (threadIdx.x & ((1 << qpwS) - 1)) << 2;
    int rpi  = 256 >> qpwS;                    // rows per iteration
    int rpb  = rpi << 2;                       // rows per block at 4 iters
    if (scale == 3) rpb = rpi << 1;            // scale3 does 2 iters

    int kh  = 512 >> scale;
    int gy  = pr * kh + slice * rpb + row;
    int gx  = (pc << kwS) + col4;
    int idx = (b << (2 * wS)) + (gy << wS) + gx;

    // Front-batch ALL loads, then accumulate.
    float4 P[4], G[4];
    P[0] = *(const float4*)(pre + idx);
    G[0] = *(const float4*)(gt  + idx);
    P[1] = *(const float4*)(pre + idx + 4096);
    G[1] = *(const float4*)(gt  + idx + 4096);
    int nit = 2;
    if (scale != 3) {
        P[2] = *(const float4*)(pre + idx + 8192);
        G[2] = *(const float4*)(gt  + idx + 8192);
        P[3] = *(const float4*)(pre + idx + 12288);
        G[3] = *(const float4*)(gt  + idx + 12288);
        nit = 4;
    }

    float sg = 0.f, spp = 0.f, cnt = 0.f, ssq = 0.f;

    #define ACC(pp, gg) { float e = fmaf((gg), -200.0f, (pp));       \
                          ssq = fmaf(e, e, ssq); sg += (gg);         \
                          if (e < 0.0f) { cnt += 1.0f; spp += (pp); } }
    #pragma unroll
    for (int it = 0; it < 4; ++it) {
        if (it < nit) {
            ACC(P[it].x, G[it].x) ACC(P[it].y, G[it].y)
            ACC(P[it].z, G[it].z) ACC(P[it].w, G[it].w)
        }
    }
    #undef ACC

    // tail: fp32 smem, single sync, warp0 finishes in double
    __shared__ float fA[256], fC[256], fQ[256];
    int tid = threadIdx.x;
    fA[tid] = fmaf(sg, 200.0f, -spp);          // sabs = 200*Sum(g) - Sum_pos(p)
    fC[tid] = cnt;
    fQ[tid] = ssq;
    __syncthreads();

    if (tid < 32) {
        double dA = 0.0, dC = 0.0, dQ = 0.0;
        #pragma unroll
        for (int j = 0; j < 8; ++j) {
            int k = tid + (j << 5);
            dA += (double)fA[k];
            dC += (double)fC[k];
            dQ += (double)fQ[k];
        }
        #pragma unroll
        for (int off = 16; off > 0; off >>= 1) {
            dA += __shfl_down_sync(0xffffffffu, dA, off);
            dC += __shfl_down_sync(0xffffffffu, dC, off);
            dQ += __shfl_down_sync(0xffffffffu, dQ, off);
        }
        if (tid == 0) {
            g_pA[bid] = dA;
            g_pC[bid] = dC;
            g_pQ[bid] = dQ;
        }
    }
}

// ---------------------------------------------------------------------------
// Per-patch argmin + weighted loss. 1 block, 128 threads (one per patch).
__global__ void k_select(float* __restrict__ out)
{
    int t = threadIdx.x;
    __shared__ double num[4];
    __shared__ int    cnt[4];
    if (t < 4) { num[t] = 0.0; cnt[t] = 0; }
    __syncthreads();

    const int base4[4] = {0, 4096, 5120, 5376};
    const int cnt4[4]  = {32, 8, 2, 1};

    double best = 1e300;
    int mi = 0;
    double ssqs[4];
    #pragma unroll
    for (int i = 0; i < 4; ++i) {
        double A = 0.0, C = 0.0, Q = 0.0;
        int s0 = base4[i] + t * cnt4[i];
        for (int s = 0; s < cnt4[i]; ++s) {
            A += g_pA[s0 + s];
            C += g_pC[s0 + s];
            Q += g_pQ[s0 + s];
        }
        ssqs[i] = Q;
        double e = A / (C + (double)0.1f);
        if (e < best) { best = e; mi = i; }   // strict < = first-min (argmin)
    }
    g_mask[t] = mi;
    atomicAdd(&num[mi], ssqs[mi]);
    atomicAdd(&cnt[mi], 1);
    __syncthreads();

    if (t == 0) {
        const double w[4]  = {0.5, 0.25, 0.125, 0.0625};
        const double pe[4] = {131072.0, 32768.0, 8192.0, 2048.0};
        double loss = 0.0;
        #pragma unroll
        for (int i = 0; i < 4; ++i)
            loss += w[i] * (num[i] / ((double)cnt[i] * pe[i] + (double)0.01f));
        out[0] = (float)loss;
    }
}

// ---------------------------------------------------------------------------
// Compose out_img & lab_img. One block = two 1024-pixel rows (2048 px),
// 2 quads per thread for gather MLP. Values staged in smem, then emitted
// with ALIGNED, WARP-CONTIGUOUS float4 streaming stores (+1 global offset
// absorbed by the smem re-alignment).
__global__ void k_write(const float* __restrict__ p0, const float* __restrict__ p1,
                        const float* __restrict__ p2, const float* __restrict__ p3,
                        const float* __restrict__ g0, const float* __restrict__ g1,
                        const float* __restrict__ g2, const float* __restrict__ g3,
                        float* __restrict__ out)
{
    __shared__ float so[2048];
    __shared__ float sl[2048];

    int t    = threadIdx.x;
    int base = blockIdx.x << 11;          // 2048-pixel chunk (2 rows)

    #pragma unroll
    for (int j = 0; j < 2; ++j) {
        int P  = base + (t << 2) + (j << 10);
        int b  = P >> 20;
        int r  = P & 1048575;
        int Y  = r >> 10;
        int X  = r & 1023;
        int pr = Y >> 9;
        int pc = X >> 8;
        int mi = g_mask[(b << 3) | (pr << 2) | pc];

        int kh = 512 >> mi;
        int kw = 256 >> mi;
        int iy = (Y & 511) - ((512 - kh) >> 1);
        int ix = (X & 255) - ((256 - kw) >> 1);

        const float PADV = 0.2f / 200.0f;
        float4 vo = make_float4(PADV, PADV, PADV, PADV);
        float4 vl = vo;

        if ((unsigned)iy < (unsigned)kh && (unsigned)ix < (unsigned)kw) {
            int ws  = 10 - mi;
            int idx = (b << (2 * ws)) + ((pr * kh + iy) << ws)
                    + (pc << (8 - mi)) + ix;
            const float* pp = (mi == 0) ? p0 : (mi == 1) ? p1 : (mi == 2) ? p2 : p3;
            const float* gg = (mi == 0) ? g0 : (mi == 1) ? g1 : (mi == 2) ? g2 : g3;
            float4 p = *(const float4*)(pp + idx);
            float4 g = *(const float4*)(gg + idx);
            vo = make_float4(p.x / 200.0f, p.y / 200.0f, p.z / 200.0f, p.w / 200.0f);
            vl = make_float4((g.x * 200.0f) / 200.0f, (g.y * 200.0f) / 200.0f,
                             (g.z * 200.0f) / 200.0f, (g.w * 200.0f) / 200.0f);
        }

        *(float4*)(so + (t << 2) + (j << 10)) = vo;
        *(float4*)(sl + (t << 2) + (j << 10)) = vl;
    }
    __syncthreads();

    float* ob = out + 1 + base;           // +1 offset: quads at k=3+4q aligned
    float* lb = ob + IMG0;                // IMG0 % 4 == 0 -> same phase

    #pragma unroll
    for (int j = 0; j < 2; ++j) {
        int q = t + (j << 8);             // CONTIGUOUS within each pass
        if (q < 511) {
            int k = 3 + (q << 2);
            float4 a = make_float4(so[k], so[k + 1], so[k + 2], so[k + 3]);
            float4 c = make_float4(sl[k], sl[k + 1], sl[k + 2], sl[k + 3]);
            __stcs((float4*)(ob + k), a);
            __stcs((float4*)(lb + k), c);
        } else if (q == 511) {
            ob[0] = so[0]; ob[1] = so[1]; ob[2] = so[2]; ob[2047] = so[2047];
            lb[0] = sl[0]; lb[1] = sl[1]; lb[2] = sl[2]; lb[2047] = sl[2047];
        }
    }
}

// ---------------------------------------------------------------------------
extern "C" void kernel_launch(void* const* d_in, const int* in_sizes, int n_in,
                              void* d_out, int out_size)
{
    const float *pre[4], *gt[4];
    if (n_in >= 8 && in_sizes[1] == in_sizes[0]) {        // interleaved
        for (int i = 0; i < 4; ++i) {
            pre[i] = (const float*)d_in[2 * i];
            gt [i] = (const float*)d_in[2 * i + 1];
        }
    } else {                                              // grouped
        for (int i = 0; i < 4; ++i) {
            pre[i] = (const float*)d_in[i];
            gt [i] = (const float*)d_in[4 + i];
        }
    }
    float* out = (float*)d_out;

    k_reduce<<<NSLOTS, 256>>>(pre[0], pre[1], pre[2], pre[3],
                              gt[0], gt[1], gt[2], gt[3]);
    k_select<<<1, 128>>>(out);
    k_write<<<8192, 256>>>(pre[0], pre[1], pre[2], pre[3],
                           gt[0], gt[1], gt[2], gt[3], out);
    (void)out_size;
}